// round 16
// baseline (speedup 1.0000x reference)
#include <cuda_runtime.h>
#include <cstdint>

#define NN 4096
#define FF 16
#define CM 512                    // X rows staged per chunk
#define XS_STRIDE (CM + 4)        // float stride per feature row (8B-aligned f2)
#define THREADS 256
#define WARPS_PER_BLOCK 8
#define R 2                       // output rows per warp
#define ROWS_PER_BLOCK (WARPS_PER_BLOCK * R)   // 16
#define TM 64                     // m per W tile
#define DEPTH 3                   // W ring depth per warp
#define NTILES (NN / TM)          // 64
#define TPC (CM / TM)             // 8 tiles per X chunk
#define WSLOT (12 * TM)           // 768 floats per (warp, depth) slot

#define SMEM_X_FLOATS (FF * XS_STRIDE)
#define SMEM_W_FLOATS (WARPS_PER_BLOCK * DEPTH * WSLOT)
#define SMEM_BYTES ((SMEM_X_FLOATS + SMEM_W_FLOATS) * 4)

__global__ void __launch_bounds__(THREADS, 2)
diffusion_conv_kernel(const float* __restrict__ X,
                      const float* __restrict__ theta,
                      const float* __restrict__ Wp,
                      const float* __restrict__ WTp,
                      float* __restrict__ out)
{
    extern __shared__ float smem[];
    float* Xs = smem;                                   // [FF][XS_STRIDE]
    float* Wb = smem + SMEM_X_FLOATS;                   // [8][DEPTH][WSLOT]

    const int tid  = threadIdx.x;
    const int warp = tid >> 5;
    const int lane = tid & 31;

    const int n0 = blockIdx.x * ROWS_PER_BLOCK + warp * R;   // first of 2 rows
    const size_t NN2 = (size_t)NN * NN;

    const float ta0 = theta[0], tb0 = theta[1];
    const float ta1 = theta[2], tb1 = theta[3];
    const float ta2 = theta[4], tb2 = theta[5];

    float* Wb_w = Wb + warp * (DEPTH * WSLOT);          // this warp's ring

    // per-lane cp.async endpoints: 6 chunks of 16B per tile
    // chunk c = k*32+lane; stream s=c>>4 (12 streams: w0,w1,w2,v0,v1,v2 row0,
    // then same row1); j=c&15 is the 16B chunk within the 256B stream-tile.
    const float* srcb[6];
    uint32_t dstb[6];
#pragma unroll
    for (int k = 0; k < 6; k++) {
        const int c  = k * 32 + lane;
        const int s  = c >> 4;
        const int j  = c & 15;
        const int s6 = (s >= 6) ? (s - 6) : s;
        const float* pb = (s6 < 3) ? (Wp + (size_t)s6 * NN2)
                                   : (WTp + (size_t)(s6 - 3) * NN2);
        pb += (size_t)n0 * NN + ((s >= 6) ? NN : 0) + j * 4;
        srcb[k] = pb;
        const float* dp = Wb_w + s * TM + j * 4;
        dstb[k] = (uint32_t)__cvta_generic_to_shared(dp);
    }

    // issue one W tile into ring slot (t % DEPTH); 6 cp.async per lane
#define ISSUE_TILE(t_)                                                        \
    {                                                                         \
        const uint32_t doff_ = (uint32_t)(((t_) % DEPTH) * (WSLOT * 4));      \
        const int soff_ = (t_) * TM;                                          \
        _Pragma("unroll")                                                     \
        for (int k = 0; k < 6; k++)                                           \
            asm volatile("cp.async.cg.shared.global [%0], [%1], 16;"          \
                         :: "r"(dstb[k] + doff_), "l"(srcb[k] + soff_));      \
    }

    float acc0[FF], acc1[FF];
#pragma unroll
    for (int f = 0; f < FF; f++) { acc0[f] = 0.0f; acc1[f] = 0.0f; }

    // prologue: start the W pipeline (tiles 0 and 1)
    ISSUE_TILE(0)
    asm volatile("cp.async.commit_group;");
    ISSUE_TILE(1)
    asm volatile("cp.async.commit_group;");

#pragma unroll 1
    for (int ch = 0; ch < NN / CM; ch++) {
        const int c0 = ch * CM;
        __syncthreads();   // previous chunk's X fully consumed

        // stage X[c0 : c0+CM][:] transposed into Xs[f][m_local]
        // (W cp.asyncs remain in flight across these barriers)
        for (int i = tid; i < CM; i += THREADS) {
            const float4* xr = (const float4*)(X + (size_t)(c0 + i) * FF);
            float4 a = xr[0], b = xr[1], c = xr[2], d = xr[3];
            Xs[ 0 * XS_STRIDE + i] = a.x;  Xs[ 1 * XS_STRIDE + i] = a.y;
            Xs[ 2 * XS_STRIDE + i] = a.z;  Xs[ 3 * XS_STRIDE + i] = a.w;
            Xs[ 4 * XS_STRIDE + i] = b.x;  Xs[ 5 * XS_STRIDE + i] = b.y;
            Xs[ 6 * XS_STRIDE + i] = b.z;  Xs[ 7 * XS_STRIDE + i] = b.w;
            Xs[ 8 * XS_STRIDE + i] = c.x;  Xs[ 9 * XS_STRIDE + i] = c.y;
            Xs[10 * XS_STRIDE + i] = c.z;  Xs[11 * XS_STRIDE + i] = c.w;
            Xs[12 * XS_STRIDE + i] = d.x;  Xs[13 * XS_STRIDE + i] = d.y;
            Xs[14 * XS_STRIDE + i] = d.z;  Xs[15 * XS_STRIDE + i] = d.w;
        }
        __syncthreads();

        // 8 W tiles per chunk; each warp runs its own async pipeline
#pragma unroll 1
        for (int tt = 0; tt < TPC; tt++) {
            const int t = ch * TPC + tt;

            // keep the ring full: issue tile t+2 (slot (t+2)%3, whose reads
            // finished at tile t-1), then commit (possibly empty group)
            if (t + 2 < NTILES) {
                ISSUE_TILE(t + 2)
            }
            asm volatile("cp.async.commit_group;");
            // groups {t, t+1, t+2} are the newest 3; wait until only 2 pend
            asm volatile("cp.async.wait_group 2;");
            __syncwarp();

            // compute tile t from ring slot t%DEPTH; lane owns m = {2l, 2l+1}
            const float* wb = Wb_w + (t % DEPTH) * WSLOT;
            const int m2 = 2 * lane;

            float2 s0  = *(const float2*)&wb[ 0 * TM + m2];
            float2 s1  = *(const float2*)&wb[ 1 * TM + m2];
            float2 s2  = *(const float2*)&wb[ 2 * TM + m2];
            float2 s3  = *(const float2*)&wb[ 3 * TM + m2];
            float2 s4  = *(const float2*)&wb[ 4 * TM + m2];
            float2 s5  = *(const float2*)&wb[ 5 * TM + m2];
            float2 s6  = *(const float2*)&wb[ 6 * TM + m2];
            float2 s7  = *(const float2*)&wb[ 7 * TM + m2];
            float2 s8  = *(const float2*)&wb[ 8 * TM + m2];
            float2 s9  = *(const float2*)&wb[ 9 * TM + m2];
            float2 s10 = *(const float2*)&wb[10 * TM + m2];
            float2 s11 = *(const float2*)&wb[11 * TM + m2];

            const float m0a = ta0 * s0.x + ta1 * s1.x + ta2 * s2.x
                            + tb0 * s3.x + tb1 * s4.x + tb2 * s5.x;
            const float m0b = ta0 * s0.y + ta1 * s1.y + ta2 * s2.y
                            + tb0 * s3.y + tb1 * s4.y + tb2 * s5.y;
            const float m1a = ta0 * s6.x + ta1 * s7.x + ta2 * s8.x
                            + tb0 * s9.x + tb1 * s10.x + tb2 * s11.x;
            const float m1b = ta0 * s6.y + ta1 * s7.y + ta2 * s8.y
                            + tb0 * s9.y + tb1 * s10.y + tb2 * s11.y;

            const int mloc = tt * TM + m2;
#pragma unroll
            for (int f = 0; f < FF; f++) {
                float2 xs = *(const float2*)&Xs[f * XS_STRIDE + mloc];
                acc0[f] += m0a * xs.x + m0b * xs.y;
                acc1[f] += m1a * xs.x + m1b * xs.y;
            }
        }
    }

    // butterfly-reduce each feature across the warp
#pragma unroll
    for (int f = 0; f < FF; f++) {
#pragma unroll
        for (int d = 16; d >= 1; d >>= 1) {
            acc0[f] += __shfl_xor_sync(0xFFFFFFFFu, acc0[f], d);
            acc1[f] += __shfl_xor_sync(0xFFFFFFFFu, acc1[f], d);
        }
    }

    if (lane == 0) {
        const float* x0 = X + (size_t)n0 * FF;
        float* o0 = out + (size_t)n0 * FF;
#pragma unroll
        for (int f = 0; f < FF; f++) {
            o0[f]      = x0[f]      + acc0[f];
            o0[FF + f] = x0[FF + f] + acc1[f];
        }
    }
}

extern "C" void kernel_launch(void* const* d_in, const int* in_sizes, int n_in,
                              void* d_out, int out_size)
{
    const float* X     = (const float*)d_in[0];   // [4096, 16]
    const float* theta = (const float*)d_in[1];   // [3, 2]
    const float* Wp    = (const float*)d_in[2];   // [3, 4096, 4096]
    const float* WTp   = (const float*)d_in[3];   // [3, 4096, 4096]
    float* out = (float*)d_out;                   // [4096, 16]

    static int attr_done = 0;
    if (!attr_done) {
        cudaFuncSetAttribute(diffusion_conv_kernel,
                             cudaFuncAttributeMaxDynamicSharedMemorySize,
                             SMEM_BYTES);
        attr_done = 1;
    }

    dim3 grid(NN / ROWS_PER_BLOCK);               // 256 blocks
    dim3 block(THREADS);
    diffusion_conv_kernel<<<grid, block, SMEM_BYTES>>>(X, theta, Wp, WTp, out);
}